// round 1
// baseline (speedup 1.0000x reference)
#include <cuda_runtime.h>

#define B_   512
#define H_   512
#define L_   512
#define I_   32
#define DT_  0.042f

#define BM   32
#define BN   64
#define BK   16
#define AP   36          // padded BM (multiple of 4 for float4-aligned rows)
#define GRID_ 128
#define NTHR 256
#define KCH  (H_ / BK)   // 32 k-chunks

// Persistent device state (3 MB total, L2-resident)
__device__ float g_hy[B_ * H_];
__device__ float g_hz[B_ * H_];
__device__ float g_T [B_ * H_];
__device__ unsigned g_bar_count = 0u;
__device__ volatile unsigned g_bar_gen = 0u;

__device__ __forceinline__ void grid_barrier(unsigned gen) {
    __syncthreads();
    if (threadIdx.x == 0) {
        __threadfence();
        if (atomicAdd(&g_bar_count, 1u) == (unsigned)(GRID_ - 1)) {
            g_bar_count = 0u;
            __threadfence();
            g_bar_gen = gen + 1u;      // release
        } else {
            while (g_bar_gen == gen) { }  // volatile spin
            __threadfence();              // acquire
        }
    }
    __syncthreads();
}

// C_tile(32x64) [SGN>0: +=, SGN<0: -=]  A[i0..i0+31, 0..511] * B[0..511, j0..j0+63]
// A, B row-major with leading dim 512. Double-buffered SMEM, reg-staged loads.
template<int SGN>
__device__ __forceinline__ void gemm_tile(
    const float* __restrict__ A, const float* __restrict__ Bm,
    int i0, int j0, int tid, int tx, int ty,
    float As[2][BK][AP], float Bs[2][BK][BN],
    float acc[4][2])
{
    float ra[2], rb[4];

    // prologue: chunk 0
    #pragma unroll
    for (int e = 0; e < 2; ++e) {
        int idx = tid + e * NTHR; int r = idx >> 4, c = idx & 15;
        ra[e] = A[(i0 + r) * H_ + c];
    }
    #pragma unroll
    for (int e = 0; e < 4; ++e) {
        int idx = tid + e * NTHR; int c = idx >> 6, jj = idx & 63;
        rb[e] = Bm[c * H_ + j0 + jj];
    }
    #pragma unroll
    for (int e = 0; e < 2; ++e) {
        int idx = tid + e * NTHR; int r = idx >> 4, c = idx & 15;
        As[0][c][r] = ra[e];
    }
    #pragma unroll
    for (int e = 0; e < 4; ++e) {
        int idx = tid + e * NTHR; int c = idx >> 6, jj = idx & 63;
        Bs[0][c][jj] = rb[e];
    }
    __syncthreads();

    for (int kc = 0; kc < KCH; ++kc) {
        const int cur = kc & 1;
        const int k0n = (kc + 1) * BK;
        if (kc + 1 < KCH) {
            #pragma unroll
            for (int e = 0; e < 2; ++e) {
                int idx = tid + e * NTHR; int r = idx >> 4, c = idx & 15;
                ra[e] = A[(i0 + r) * H_ + k0n + c];
            }
            #pragma unroll
            for (int e = 0; e < 4; ++e) {
                int idx = tid + e * NTHR; int c = idx >> 6, jj = idx & 63;
                rb[e] = Bm[(k0n + c) * H_ + j0 + jj];
            }
        }
        #pragma unroll
        for (int kk = 0; kk < BK; ++kk) {
            float4 a = *reinterpret_cast<const float4*>(&As[cur][kk][ty * 4]);
            float2 b = *reinterpret_cast<const float2*>(&Bs[cur][kk][tx * 2]);
            if (SGN > 0) {
                acc[0][0] += a.x * b.x; acc[0][1] += a.x * b.y;
                acc[1][0] += a.y * b.x; acc[1][1] += a.y * b.y;
                acc[2][0] += a.z * b.x; acc[2][1] += a.z * b.y;
                acc[3][0] += a.w * b.x; acc[3][1] += a.w * b.y;
            } else {
                acc[0][0] -= a.x * b.x; acc[0][1] -= a.x * b.y;
                acc[1][0] -= a.y * b.x; acc[1][1] -= a.y * b.y;
                acc[2][0] -= a.z * b.x; acc[2][1] -= a.z * b.y;
                acc[3][0] -= a.w * b.x; acc[3][1] -= a.w * b.y;
            }
        }
        if (kc + 1 < KCH) {
            const int nb = cur ^ 1;
            #pragma unroll
            for (int e = 0; e < 2; ++e) {
                int idx = tid + e * NTHR; int r = idx >> 4, c = idx & 15;
                As[nb][c][r] = ra[e];
            }
            #pragma unroll
            for (int e = 0; e < 4; ++e) {
                int idx = tid + e * NTHR; int c = idx >> 6, jj = idx & 63;
                Bs[nb][c][jj] = rb[e];
            }
        }
        __syncthreads();
    }
}

__global__ void __launch_bounds__(NTHR, 1) coesn_kernel(
    const float* __restrict__ x,    const float* __restrict__ x2h,
    const float* __restrict__ h2h,  const float* __restrict__ h2hT,
    const float* __restrict__ bias, const float* __restrict__ gamma,
    const float* __restrict__ eps,  float* __restrict__ out, int write_final)
{
    __shared__ __align__(16) float As[2][BK][AP];
    __shared__ __align__(16) float Bs[2][BK][BN];
    __shared__ __align__(16) float Xs[I_][AP];
    __shared__ __align__(16) float X2s[I_][BN];

    const int tid = threadIdx.x;
    const int tx = tid & 31, ty = tid >> 5;
    const int bid = blockIdx.x;
    const int i0 = (bid >> 3) * BM;   // 16 row tiles
    const int j0 = (bid & 7) * BN;    // 8 col tiles

    unsigned gen = g_bar_gen;         // barrier generation persists across graph replays

    // persistent per-CTA data: x2h column slice, per-thread scalars
    #pragma unroll
    for (int e = 0; e < 8; ++e) {
        int idx = tid + e * NTHR; int p = idx >> 6, jj = idx & 63;
        X2s[p][jj] = x2h[p * H_ + j0 + jj];
    }
    const int jc = j0 + tx * 2;
    float bias_r[2] = { bias[jc],  bias[jc + 1]  };
    float gam_r[2]  = { gamma[jc], gamma[jc + 1] };
    float eps_r[2]  = { eps[jc],   eps[jc + 1]   };

    // zero state tile (re-run every launch/replay)
    #pragma unroll
    for (int e = 0; e < 8; ++e) {
        int idx = tid + e * NTHR; int r = idx >> 6, cc = idx & 63;
        g_hy[(i0 + r) * H_ + j0 + cc] = 0.f;
        g_hz[(i0 + r) * H_ + j0 + cc] = 0.f;
    }
    grid_barrier(gen); gen++;

    for (int t = 0; t < L_; ++t) {
        // ---- Phase 1: T = tanh(hy @ h2h + bias) ----
        float acc[4][2] = {{0.f,0.f},{0.f,0.f},{0.f,0.f},{0.f,0.f}};
        gemm_tile<1>(g_hy, h2h, i0, j0, tid, tx, ty, As, Bs, acc);
        #pragma unroll
        for (int m = 0; m < 4; ++m) {
            int row = i0 + ty * 4 + m;
            #pragma unroll
            for (int n = 0; n < 2; ++n)
                g_T[row * H_ + jc + n] = tanhf(acc[m][n] + bias_r[n]);
        }
        grid_barrier(gen); gen++;

        // ---- Phase 2: hz/hy update ----
        // x_t tile -> SMEM (transposed)
        #pragma unroll
        for (int e = 0; e < 4; ++e) {
            int idx = tid + e * NTHR; int r = idx >> 5, p = idx & 31;
            Xs[p][r] = x[(i0 + r) * (L_ * I_) + t * I_ + p];
        }
        __syncthreads();

        float ac2[4][2] = {{0.f,0.f},{0.f,0.f},{0.f,0.f},{0.f,0.f}};
        // + x_t @ x2h  (K = 32)
        #pragma unroll
        for (int p = 0; p < I_; ++p) {
            float4 a = *reinterpret_cast<const float4*>(&Xs[p][ty * 4]);
            float2 b = *reinterpret_cast<const float2*>(&X2s[p][tx * 2]);
            ac2[0][0] += a.x * b.x; ac2[0][1] += a.x * b.y;
            ac2[1][0] += a.y * b.x; ac2[1][1] += a.y * b.y;
            ac2[2][0] += a.z * b.x; ac2[2][1] += a.z * b.y;
            ac2[3][0] += a.w * b.x; ac2[3][1] += a.w * b.y;
        }
        // - h2h_T @ T  (K = 512)
        gemm_tile<-1>(h2hT, g_T, i0, j0, tid, tx, ty, As, Bs, ac2);

        // epilogue: integrate, write all_states
        #pragma unroll
        for (int m = 0; m < 4; ++m) {
            int row = i0 + ty * 4 + m;
            int obase = (row * L_ + t) * H_ + jc;
            #pragma unroll
            for (int n = 0; n < 2; ++n) {
                int idx = row * H_ + jc + n;
                float hyv = g_hy[idx], hzv = g_hz[idx];
                float hzn = hzv + DT_ * (ac2[m][n] - gam_r[n] * hyv - eps_r[n] * hzv);
                float hyn = hyv + DT_ * hzn;
                g_hz[idx] = hzn;
                g_hy[idx] = hyn;
                out[obase + n] = hyn;
            }
        }
        grid_barrier(gen); gen++;
    }

    // final hy (second output), if the harness expects it
    if (write_final) {
        #pragma unroll
        for (int e = 0; e < 8; ++e) {
            int idx = tid + e * NTHR; int r = idx >> 6, cc = idx & 63;
            int gi = (i0 + r) * H_ + j0 + cc;
            out[B_ * L_ * H_ + gi] = g_hy[gi];
        }
    }
}

extern "C" void kernel_launch(void* const* d_in, const int* in_sizes, int n_in,
                              void* d_out, int out_size) {
    const float* x    = (const float*)d_in[0];
    const float* x2h  = (const float*)d_in[1];
    const float* h2h  = (const float*)d_in[2];
    const float* h2hT = (const float*)d_in[3];
    const float* bias = (const float*)d_in[4];
    const float* gam  = (const float*)d_in[5];
    const float* eps  = (const float*)d_in[6];
    (void)in_sizes; (void)n_in;

    const int write_final = (out_size >= B_ * L_ * H_ + B_ * H_) ? 1 : 0;
    coesn_kernel<<<GRID_, NTHR>>>(x, x2h, h2h, h2hT, bias, gam, eps,
                                  (float*)d_out, write_final);
}